// round 12
// baseline (speedup 1.0000x reference)
#include <cuda_runtime.h>

#define BATCH 32
#define NPTS  16384
#define GRP   128
#define KNN   64
#define HID   128
#define DIM   384

// Scratch (no allocations allowed)
__device__ float g_cent[BATCH * GRP * 3];
__device__ float g_hbar[BATCH * GRP * HID];

// ---------------------------------------------------------------------------
// Kernel 1: Farthest point sampling. One block per batch, 512 threads.
// Points live in registers (32/thread), running min-distance lives in SMEM
// (thread-private slots, strided layout -> conflict-free).
// Matches reference: idx[0]=0, emit current farthest BEFORE distance update,
// argmax picks lowest index on exact ties.
// ---------------------------------------------------------------------------
__global__ __launch_bounds__(512) void fps_kernel(const float* __restrict__ pts,
                                                  float* __restrict__ out_cent) {
    extern __shared__ unsigned char dyn_smem[];
    float* sdist = reinterpret_cast<float*>(dyn_smem);  // NPTS floats
    __shared__ float scx, scy, scz;
    __shared__ int snext;
    __shared__ float swv[16];
    __shared__ int swi[16];

    const int b = blockIdx.x;
    const float* P = pts + (size_t)b * NPTS * 3;
    const int t = threadIdx.x;

    float px[32], py[32], pz[32];
#pragma unroll
    for (int j = 0; j < 32; j++) {
        int idx = t + j * 512;
        px[j] = P[idx * 3 + 0];
        py[j] = P[idx * 3 + 1];
        pz[j] = P[idx * 3 + 2];
        sdist[idx] = 3.4e38f;
    }
    __syncthreads();

    int cur = 0;
    for (int g = 0; g < GRP; g++) {
        // broadcast coords of current farthest point
        if (t == (cur & 511)) {
            int j = cur >> 9;
            scx = px[j]; scy = py[j]; scz = pz[j];
        }
        __syncthreads();
        float cx = scx, cy = scy, cz = scz;

        if (t == 0) {
            size_t o = ((size_t)b * GRP + g) * 3;
            g_cent[o + 0] = cx; g_cent[o + 1] = cy; g_cent[o + 2] = cz;
            if (out_cent) {
                out_cent[o + 0] = cx; out_cent[o + 1] = cy; out_cent[o + 2] = cz;
            }
        }

        float bv = -1.0f;
        int bi = 0x7fffffff;
#pragma unroll
        for (int j = 0; j < 32; j++) {
            int idx = t + j * 512;
            float dx = px[j] - cx;
            float dy = py[j] - cy;
            float dz = pz[j] - cz;
            float d = dx * dx + dy * dy + dz * dz;
            float nd = fminf(sdist[idx], d);
            sdist[idx] = nd;
            if (nd > bv) { bv = nd; bi = idx; }  // idx ascending within thread
        }
        // warp argmax (tie -> lower index)
#pragma unroll
        for (int off = 16; off; off >>= 1) {
            float ov = __shfl_down_sync(0xffffffffu, bv, off);
            int oi = __shfl_down_sync(0xffffffffu, bi, off);
            if (ov > bv || (ov == bv && oi < bi)) { bv = ov; bi = oi; }
        }
        if ((t & 31) == 0) { swv[t >> 5] = bv; swi[t >> 5] = bi; }
        __syncthreads();
        if (t < 16) {
            bv = swv[t]; bi = swi[t];
#pragma unroll
            for (int off = 8; off; off >>= 1) {
                float ov = __shfl_down_sync(0x0000ffffu, bv, off);
                int oi = __shfl_down_sync(0x0000ffffu, bi, off);
                if (ov > bv || (ov == bv && oi < bi)) { bv = ov; bi = oi; }
            }
            if (t == 0) snext = bi;
        }
        __syncthreads();
        cur = snext;
    }
}

// ---------------------------------------------------------------------------
// Kernel 2: per-(b,g) exact top-64 smallest dist2 (radix select, matching
// lax.top_k stable tie semantics), then fused gelu-MLP first layer and mean
// over the 64 neighbors -> g_hbar[b*GRP+g][128].
// ---------------------------------------------------------------------------
__global__ __launch_bounds__(256) void group_kernel(const float* __restrict__ pts,
                                                    const float* __restrict__ w1,
                                                    const float* __restrict__ b1) {
    extern __shared__ unsigned char dyn_smem[];
    unsigned* s_keys = reinterpret_cast<unsigned*>(dyn_smem);  // NPTS keys

    __shared__ unsigned hist[256];
    __shared__ unsigned s_prefix;
    __shared__ int s_k;
    __shared__ int sel[KNN];
    __shared__ int eql[KNN];
    __shared__ int s_nless, s_neq;
    __shared__ float loc[KNN][3];
    __shared__ float hpart[256];

    const int g = blockIdx.x;
    const int b = blockIdx.y;
    const int t = threadIdx.x;

    const float* P = pts + (size_t)b * NPTS * 3;
    const float* C = g_cent + ((size_t)b * GRP + g) * 3;
    const float cx = C[0], cy = C[1], cz = C[2];
    const float c2 = cx * cx + cy * cy + cz * cz;

    // distances -> orderable uint keys in SMEM (reference formula)
    for (int i = t; i < NPTS; i += 256) {
        float x = P[i * 3 + 0], y = P[i * 3 + 1], z = P[i * 3 + 2];
        float p2 = x * x + y * y + z * z;
        float dot = cx * x + cy * y + cz * z;
        float f = (c2 + p2) - 2.0f * dot;
        unsigned u = __float_as_uint(f);
        u = (u & 0x80000000u) ? ~u : (u | 0x80000000u);
        s_keys[i] = u;
    }

    // 4-round MSB radix select: exact key of the 64th smallest
    unsigned prefix = 0;
    int k = KNN;
    for (int shift = 24; shift >= 0; shift -= 8) {
        hist[t & 255] = 0;  // 256 threads -> each zeros one bin
        __syncthreads();
        unsigned hmask = (shift == 24) ? 0u : (0xFFFFFFFFu << (shift + 8));
        for (int i = t; i < NPTS; i += 256) {
            unsigned key = s_keys[i];
            if ((key & hmask) == prefix)
                atomicAdd(&hist[(key >> shift) & 255u], 1u);
        }
        __syncthreads();
        if (t == 0) {
            unsigned cum = 0;
            for (int bin = 0; bin < 256; bin++) {
                unsigned c = hist[bin];
                if (cum + c >= (unsigned)k) {
                    s_k = k - (int)cum;
                    s_prefix = prefix | ((unsigned)bin << shift);
                    break;
                }
                cum += c;
            }
        }
        __syncthreads();
        prefix = s_prefix;
        k = s_k;
        __syncthreads();
    }
    const unsigned T = prefix;

    // gather: all keys < T, then fill with lowest-index ties == T
    if (t == 0) { s_nless = 0; s_neq = 0; }
    __syncthreads();
    for (int i = t; i < NPTS; i += 256) {
        unsigned key = s_keys[i];
        if (key < T) {
            int p = atomicAdd(&s_nless, 1);
            sel[p] = i;
        } else if (key == T) {
            int e = atomicAdd(&s_neq, 1);
            if (e < KNN) eql[e] = i;
        }
    }
    __syncthreads();
    if (t == 0) {
        int nless = s_nless;
        int need = KNN - nless;
        int m = (s_neq < KNN) ? s_neq : KNN;
        for (int a = 1; a < m; a++) {  // insertion sort (tiny)
            int v = eql[a];
            int c = a - 1;
            while (c >= 0 && eql[c] > v) { eql[c + 1] = eql[c]; c--; }
            eql[c + 1] = v;
        }
        for (int a = 0; a < need; a++) sel[nless + a] = eql[a];
    }
    __syncthreads();

    // local coords of selected neighbors
    if (t < KNN) {
        int idx = sel[t];
        loc[t][0] = P[idx * 3 + 0] - cx;
        loc[t][1] = P[idx * 3 + 1] - cy;
        loc[t][2] = P[idx * 3 + 2] - cz;
    }
    __syncthreads();

    // hbar[j] = mean_k gelu(loc_k . w1[:,j] + b1[j]); exact-erf gelu.
    // 256 threads: (j = t&127) x (half of k).
    const int j = t & 127;
    const float wx = w1[j], wy = w1[HID + j], wz = w1[2 * HID + j], bb = b1[j];
    float acc = 0.0f;
    const int k0 = (t >> 7) * 32;
#pragma unroll
    for (int kk = 0; kk < 32; kk++) {
        int kp = k0 + kk;
        float v = loc[kp][0] * wx + loc[kp][1] * wy + loc[kp][2] * wz + bb;
        float h = 0.5f * v * (1.0f + erff(v * 0.7071067811865476f));
        acc += h;
    }
    hpart[t] = acc;
    __syncthreads();
    if (t < HID)
        g_hbar[((size_t)b * GRP + g) * HID + t] =
            (hpart[t] + hpart[t + 128]) * (1.0f / (float)KNN);
}

// ---------------------------------------------------------------------------
// Kernel 3: tokens = hbar @ w2 + b2 (4096x384x128 GEMM), then LayerNorm.
// 16 rows per block, 384 threads (one output column each).
// ---------------------------------------------------------------------------
__global__ __launch_bounds__(384) void head_kernel(const float* __restrict__ w2,
                                                   const float* __restrict__ b2,
                                                   const float* __restrict__ gamma,
                                                   const float* __restrict__ beta,
                                                   float* __restrict__ out_tok) {
    __shared__ float sh[16 * HID];
    __shared__ float tok[16][DIM];

    const int row0 = blockIdx.x * 16;
    const int t = threadIdx.x;

    for (int i = t; i < 16 * HID; i += 384)
        sh[i] = g_hbar[(size_t)row0 * HID + i];
    __syncthreads();

    float acc[16];
#pragma unroll
    for (int r = 0; r < 16; r++) acc[r] = 0.0f;

    for (int jj = 0; jj < HID; jj++) {
        float w = w2[jj * DIM + t];
#pragma unroll
        for (int r = 0; r < 16; r++) acc[r] += sh[r * HID + jj] * w;
    }
    const float bd = b2[t];
#pragma unroll
    for (int r = 0; r < 16; r++) tok[r][t] = acc[r] + bd;
    __syncthreads();

    // LayerNorm per row: 12 warps cover 16 rows
    const int w = t >> 5, lane = t & 31;
    for (int r = w; r < 16; r += 12) {
        float s = 0.0f;
        for (int c = lane; c < DIM; c += 32) s += tok[r][c];
#pragma unroll
        for (int off = 16; off; off >>= 1) s += __shfl_xor_sync(0xffffffffu, s, off);
        float mu = s * (1.0f / DIM);
        float v = 0.0f;
        for (int c = lane; c < DIM; c += 32) {
            float d0 = tok[r][c] - mu;
            v += d0 * d0;
        }
#pragma unroll
        for (int off = 16; off; off >>= 1) v += __shfl_xor_sync(0xffffffffu, v, off);
        float rstd = rsqrtf(v * (1.0f / DIM) + 1e-5f);
        for (int c = lane; c < DIM; c += 32)
            out_tok[((size_t)row0 + r) * DIM + c] =
                (tok[r][c] - mu) * rstd * gamma[c] + beta[c];
    }
}

// ---------------------------------------------------------------------------
extern "C" void kernel_launch(void* const* d_in, const int* in_sizes, int n_in,
                              void* d_out, int out_size) {
    const float* pts   = (const float*)d_in[0];  // [32,16384,3]
    const float* w1    = (const float*)d_in[1];  // [3,128]
    const float* b1    = (const float*)d_in[2];  // [128]
    const float* w2    = (const float*)d_in[3];  // [128,384]
    const float* b2    = (const float*)d_in[4];  // [384]
    const float* gamma = (const float*)d_in[5];  // [384]
    const float* beta  = (const float*)d_in[6];  // [384]

    float* out = (float*)d_out;
    float* out_cent = nullptr;
    float* out_tok = out;
    // Expected layout: centroids [32,128,3] then tokens_ln [32,128,384]
    if (out_size == BATCH * GRP * (3 + DIM)) {
        out_cent = out;
        out_tok = out + BATCH * GRP * 3;
    }

    cudaFuncSetAttribute(fps_kernel, cudaFuncAttributeMaxDynamicSharedMemorySize,
                         NPTS * (int)sizeof(float));
    cudaFuncSetAttribute(group_kernel, cudaFuncAttributeMaxDynamicSharedMemorySize,
                         NPTS * (int)sizeof(unsigned));

    fps_kernel<<<BATCH, 512, NPTS * sizeof(float)>>>(pts, out_cent);
    group_kernel<<<dim3(GRP, BATCH), 256, NPTS * sizeof(unsigned)>>>(pts, w1, b1);
    head_kernel<<<(BATCH * GRP) / 16, 384>>>(w2, b2, gamma, beta, out_tok);
}

// round 13
// speedup vs baseline: 1.0009x; 1.0009x over previous
#include <cuda_runtime.h>

#define BATCH 32
#define NPTS  16384
#define GRP   128
#define KNN   64
#define HID   128
#define DIM   384

// Scratch (no allocations allowed)
__device__ float g_cent[BATCH * GRP * 3];
__device__ float g_hbar[BATCH * GRP * HID];

// ---------------------------------------------------------------------------
// Kernel 1: Farthest point sampling. One block per batch, 512 threads.
// Points live in registers (32/thread), running min-distance lives in SMEM
// (thread-private slots, strided layout -> conflict-free).
// Matches reference: idx[0]=0, emit current farthest BEFORE distance update,
// argmax picks lowest index on exact ties.
// ---------------------------------------------------------------------------
__global__ __launch_bounds__(512) void fps_kernel(const float* __restrict__ pts,
                                                  float* __restrict__ out_cent) {
    extern __shared__ unsigned char dyn_smem[];
    float* sdist = reinterpret_cast<float*>(dyn_smem);  // NPTS floats
    __shared__ float scx, scy, scz;
    __shared__ int snext;
    __shared__ float swv[16];
    __shared__ int swi[16];

    const int b = blockIdx.x;
    const float* P = pts + (size_t)b * NPTS * 3;
    const int t = threadIdx.x;

    float px[32], py[32], pz[32];
#pragma unroll
    for (int j = 0; j < 32; j++) {
        int idx = t + j * 512;
        px[j] = P[idx * 3 + 0];
        py[j] = P[idx * 3 + 1];
        pz[j] = P[idx * 3 + 2];
        sdist[idx] = 3.4e38f;
    }
    __syncthreads();

    int cur = 0;
    for (int g = 0; g < GRP; g++) {
        // broadcast coords of current farthest point
        if (t == (cur & 511)) {
            int j = cur >> 9;
            scx = px[j]; scy = py[j]; scz = pz[j];
        }
        __syncthreads();
        float cx = scx, cy = scy, cz = scz;

        if (t == 0) {
            size_t o = ((size_t)b * GRP + g) * 3;
            g_cent[o + 0] = cx; g_cent[o + 1] = cy; g_cent[o + 2] = cz;
            if (out_cent) {
                out_cent[o + 0] = cx; out_cent[o + 1] = cy; out_cent[o + 2] = cz;
            }
        }

        float bv = -1.0f;
        int bi = 0x7fffffff;
#pragma unroll
        for (int j = 0; j < 32; j++) {
            int idx = t + j * 512;
            float dx = px[j] - cx;
            float dy = py[j] - cy;
            float dz = pz[j] - cz;
            float d = dx * dx + dy * dy + dz * dz;
            float nd = fminf(sdist[idx], d);
            sdist[idx] = nd;
            if (nd > bv) { bv = nd; bi = idx; }  // idx ascending within thread
        }
        // warp argmax (tie -> lower index)
#pragma unroll
        for (int off = 16; off; off >>= 1) {
            float ov = __shfl_down_sync(0xffffffffu, bv, off);
            int oi = __shfl_down_sync(0xffffffffu, bi, off);
            if (ov > bv || (ov == bv && oi < bi)) { bv = ov; bi = oi; }
        }
        if ((t & 31) == 0) { swv[t >> 5] = bv; swi[t >> 5] = bi; }
        __syncthreads();
        if (t < 16) {
            bv = swv[t]; bi = swi[t];
#pragma unroll
            for (int off = 8; off; off >>= 1) {
                float ov = __shfl_down_sync(0x0000ffffu, bv, off);
                int oi = __shfl_down_sync(0x0000ffffu, bi, off);
                if (ov > bv || (ov == bv && oi < bi)) { bv = ov; bi = oi; }
            }
            if (t == 0) snext = bi;
        }
        __syncthreads();
        cur = snext;
    }
}

// ---------------------------------------------------------------------------
// Kernel 2: per-(b,g) exact top-64 smallest dist2 (radix select, matching
// lax.top_k stable tie semantics), then fused gelu-MLP first layer and mean
// over the 64 neighbors -> g_hbar[b*GRP+g][128].
// ---------------------------------------------------------------------------
__global__ __launch_bounds__(256) void group_kernel(const float* __restrict__ pts,
                                                    const float* __restrict__ w1,
                                                    const float* __restrict__ b1) {
    extern __shared__ unsigned char dyn_smem[];
    unsigned* s_keys = reinterpret_cast<unsigned*>(dyn_smem);  // NPTS keys

    __shared__ unsigned hist[256];
    __shared__ unsigned s_prefix;
    __shared__ int s_k;
    __shared__ int sel[KNN];
    __shared__ int eql[KNN];
    __shared__ int s_nless, s_neq;
    __shared__ float loc[KNN][3];
    __shared__ float hpart[256];

    const int g = blockIdx.x;
    const int b = blockIdx.y;
    const int t = threadIdx.x;

    const float* P = pts + (size_t)b * NPTS * 3;
    const float* C = g_cent + ((size_t)b * GRP + g) * 3;
    const float cx = C[0], cy = C[1], cz = C[2];
    const float c2 = cx * cx + cy * cy + cz * cz;

    // distances -> orderable uint keys in SMEM (reference formula)
    for (int i = t; i < NPTS; i += 256) {
        float x = P[i * 3 + 0], y = P[i * 3 + 1], z = P[i * 3 + 2];
        float p2 = x * x + y * y + z * z;
        float dot = cx * x + cy * y + cz * z;
        float f = (c2 + p2) - 2.0f * dot;
        unsigned u = __float_as_uint(f);
        u = (u & 0x80000000u) ? ~u : (u | 0x80000000u);
        s_keys[i] = u;
    }

    // 4-round MSB radix select: exact key of the 64th smallest
    unsigned prefix = 0;
    int k = KNN;
    for (int shift = 24; shift >= 0; shift -= 8) {
        hist[t & 255] = 0;  // 256 threads -> each zeros one bin
        __syncthreads();
        unsigned hmask = (shift == 24) ? 0u : (0xFFFFFFFFu << (shift + 8));
        for (int i = t; i < NPTS; i += 256) {
            unsigned key = s_keys[i];
            if ((key & hmask) == prefix)
                atomicAdd(&hist[(key >> shift) & 255u], 1u);
        }
        __syncthreads();
        if (t == 0) {
            unsigned cum = 0;
            for (int bin = 0; bin < 256; bin++) {
                unsigned c = hist[bin];
                if (cum + c >= (unsigned)k) {
                    s_k = k - (int)cum;
                    s_prefix = prefix | ((unsigned)bin << shift);
                    break;
                }
                cum += c;
            }
        }
        __syncthreads();
        prefix = s_prefix;
        k = s_k;
        __syncthreads();
    }
    const unsigned T = prefix;

    // gather: all keys < T, then fill with lowest-index ties == T
    if (t == 0) { s_nless = 0; s_neq = 0; }
    __syncthreads();
    for (int i = t; i < NPTS; i += 256) {
        unsigned key = s_keys[i];
        if (key < T) {
            int p = atomicAdd(&s_nless, 1);
            sel[p] = i;
        } else if (key == T) {
            int e = atomicAdd(&s_neq, 1);
            if (e < KNN) eql[e] = i;
        }
    }
    __syncthreads();
    if (t == 0) {
        int nless = s_nless;
        int need = KNN - nless;
        int m = (s_neq < KNN) ? s_neq : KNN;
        for (int a = 1; a < m; a++) {  // insertion sort (tiny)
            int v = eql[a];
            int c = a - 1;
            while (c >= 0 && eql[c] > v) { eql[c + 1] = eql[c]; c--; }
            eql[c + 1] = v;
        }
        for (int a = 0; a < need; a++) sel[nless + a] = eql[a];
    }
    __syncthreads();

    // local coords of selected neighbors
    if (t < KNN) {
        int idx = sel[t];
        loc[t][0] = P[idx * 3 + 0] - cx;
        loc[t][1] = P[idx * 3 + 1] - cy;
        loc[t][2] = P[idx * 3 + 2] - cz;
    }
    __syncthreads();

    // hbar[j] = mean_k gelu(loc_k . w1[:,j] + b1[j]); exact-erf gelu.
    // 256 threads: (j = t&127) x (half of k).
    const int j = t & 127;
    const float wx = w1[j], wy = w1[HID + j], wz = w1[2 * HID + j], bb = b1[j];
    float acc = 0.0f;
    const int k0 = (t >> 7) * 32;
#pragma unroll
    for (int kk = 0; kk < 32; kk++) {
        int kp = k0 + kk;
        float v = loc[kp][0] * wx + loc[kp][1] * wy + loc[kp][2] * wz + bb;
        float h = 0.5f * v * (1.0f + erff(v * 0.7071067811865476f));
        acc += h;
    }
    hpart[t] = acc;
    __syncthreads();
    if (t < HID)
        g_hbar[((size_t)b * GRP + g) * HID + t] =
            (hpart[t] + hpart[t + 128]) * (1.0f / (float)KNN);
}

// ---------------------------------------------------------------------------
// Kernel 3: tokens = hbar @ w2 + b2 (4096x384x128 GEMM), then LayerNorm.
// 16 rows per block, 384 threads (one output column each).
// ---------------------------------------------------------------------------
__global__ __launch_bounds__(384) void head_kernel(const float* __restrict__ w2,
                                                   const float* __restrict__ b2,
                                                   const float* __restrict__ gamma,
                                                   const float* __restrict__ beta,
                                                   float* __restrict__ out_tok) {
    __shared__ float sh[16 * HID];
    __shared__ float tok[16][DIM];

    const int row0 = blockIdx.x * 16;
    const int t = threadIdx.x;

    for (int i = t; i < 16 * HID; i += 384)
        sh[i] = g_hbar[(size_t)row0 * HID + i];
    __syncthreads();

    float acc[16];
#pragma unroll
    for (int r = 0; r < 16; r++) acc[r] = 0.0f;

    for (int jj = 0; jj < HID; jj++) {
        float w = w2[jj * DIM + t];
#pragma unroll
        for (int r = 0; r < 16; r++) acc[r] += sh[r * HID + jj] * w;
    }
    const float bd = b2[t];
#pragma unroll
    for (int r = 0; r < 16; r++) tok[r][t] = acc[r] + bd;
    __syncthreads();

    // LayerNorm per row: 12 warps cover 16 rows
    const int w = t >> 5, lane = t & 31;
    for (int r = w; r < 16; r += 12) {
        float s = 0.0f;
        for (int c = lane; c < DIM; c += 32) s += tok[r][c];
#pragma unroll
        for (int off = 16; off; off >>= 1) s += __shfl_xor_sync(0xffffffffu, s, off);
        float mu = s * (1.0f / DIM);
        float v = 0.0f;
        for (int c = lane; c < DIM; c += 32) {
            float d0 = tok[r][c] - mu;
            v += d0 * d0;
        }
#pragma unroll
        for (int off = 16; off; off >>= 1) v += __shfl_xor_sync(0xffffffffu, v, off);
        float rstd = rsqrtf(v * (1.0f / DIM) + 1e-5f);
        for (int c = lane; c < DIM; c += 32)
            out_tok[((size_t)row0 + r) * DIM + c] =
                (tok[r][c] - mu) * rstd * gamma[c] + beta[c];
    }
}

// ---------------------------------------------------------------------------
extern "C" void kernel_launch(void* const* d_in, const int* in_sizes, int n_in,
                              void* d_out, int out_size) {
    const float* pts   = (const float*)d_in[0];  // [32,16384,3]
    const float* w1    = (const float*)d_in[1];  // [3,128]
    const float* b1    = (const float*)d_in[2];  // [128]
    const float* w2    = (const float*)d_in[3];  // [128,384]
    const float* b2    = (const float*)d_in[4];  // [384]
    const float* gamma = (const float*)d_in[5];  // [384]
    const float* beta  = (const float*)d_in[6];  // [384]

    float* out = (float*)d_out;
    float* out_cent = nullptr;
    float* out_tok = out;
    // Expected layout: centroids [32,128,3] then tokens_ln [32,128,384]
    if (out_size == BATCH * GRP * (3 + DIM)) {
        out_cent = out;
        out_tok = out + BATCH * GRP * 3;
    }

    cudaFuncSetAttribute(fps_kernel, cudaFuncAttributeMaxDynamicSharedMemorySize,
                         NPTS * (int)sizeof(float));
    cudaFuncSetAttribute(group_kernel, cudaFuncAttributeMaxDynamicSharedMemorySize,
                         NPTS * (int)sizeof(unsigned));

    fps_kernel<<<BATCH, 512, NPTS * sizeof(float)>>>(pts, out_cent);
    group_kernel<<<dim3(GRP, BATCH), 256, NPTS * sizeof(unsigned)>>>(pts, w1, b1);
    head_kernel<<<(BATCH * GRP) / 16, 384>>>(w2, b2, gamma, beta, out_tok);
}

// round 14
// speedup vs baseline: 1.1382x; 1.1372x over previous
#include <cuda_runtime.h>

#define BATCH 32
#define NPTS  16384
#define GRP   128
#define KNN   64
#define HID   128
#define DIM   384

#define FPS_CTAS    4
#define FPS_THREADS 512
#define FPS_PTS     (NPTS / FPS_CTAS)        // 4096
#define FPS_PPT     (FPS_PTS / FPS_THREADS)  // 8

// Scratch (no allocations allowed)
__device__ float g_cent[BATCH * GRP * 3];
__device__ float g_hbar[BATCH * GRP * HID];

__device__ __forceinline__ unsigned smem_u32(const void* p) {
    return (unsigned)__cvta_generic_to_shared(p);
}
__device__ __forceinline__ unsigned cluster_rank() {
    unsigned r;
    asm("mov.u32 %0, %%cluster_ctarank;" : "=r"(r));
    return r;
}
__device__ __forceinline__ unsigned mapa_u32(unsigned addr, unsigned rank) {
    unsigned r;
    asm("mapa.shared::cluster.u32 %0, %1, %2;" : "=r"(r) : "r"(addr), "r"(rank));
    return r;
}

// ---------------------------------------------------------------------------
// Kernel 1: Farthest point sampling, 4-CTA cluster per batch.
// Each CTA owns 4096 points (8/thread, coords+dist in registers; coords also
// mirrored in SMEM for winner lookup). Per round: intra-CTA argmax, exchange
// {x,y,z,val,idx} candidates via DSMEM (double-buffered by round parity),
// one cluster barrier, then every thread combines the 4 candidates.
// Tie rules identical to reference: max value, lowest global index.
// ---------------------------------------------------------------------------
__global__ __launch_bounds__(FPS_THREADS) __cluster_dims__(FPS_CTAS, 1, 1)
void fps_kernel(const float* __restrict__ pts, float* __restrict__ out_cent) {
    extern __shared__ unsigned char dsm[];
    float* sx = reinterpret_cast<float*>(dsm);       // [4096]
    float* sy = sx + FPS_PTS;
    float* sz = sy + FPS_PTS;
    __shared__ float4 cand[2][FPS_CTAS];   // {x, y, z, val}
    __shared__ int    candi[2][FPS_CTAS];  // global idx
    __shared__ float  swv[16];
    __shared__ int    swi[16];

    const unsigned rank = cluster_rank();
    const int b = blockIdx.x / FPS_CTAS;
    const int t = threadIdx.x;
    const float* P = pts + (size_t)b * NPTS * 3;
    const int base = (int)rank * FPS_PTS;

    float px[FPS_PPT], py[FPS_PPT], pz[FPS_PPT], dist[FPS_PPT];
#pragma unroll
    for (int j = 0; j < FPS_PPT; j++) {
        int idx = t + j * FPS_THREADS;
        int gi = base + idx;
        px[j] = P[gi * 3 + 0];
        py[j] = P[gi * 3 + 1];
        pz[j] = P[gi * 3 + 2];
        sx[idx] = px[j]; sy[idx] = py[j]; sz[idx] = pz[j];
        dist[j] = 3.4e38f;
    }
    __syncthreads();

    // start: farthest = index 0 (rank 0 owns it); every CTA reads coords.
    float cx = P[0], cy = P[1], cz = P[2];

    for (int g = 0; g < GRP; g++) {
        if (rank == 0 && t == 0) {
            size_t o = ((size_t)b * GRP + g) * 3;
            g_cent[o + 0] = cx; g_cent[o + 1] = cy; g_cent[o + 2] = cz;
            if (out_cent) {
                out_cent[o + 0] = cx; out_cent[o + 1] = cy; out_cent[o + 2] = cz;
            }
        }

        float bv = -1.0f;
        int bi = 0x7fffffff;
#pragma unroll
        for (int j = 0; j < FPS_PPT; j++) {
            float dx = px[j] - cx;
            float dy = py[j] - cy;
            float dz = pz[j] - cz;
            float d = dx * dx + dy * dy + dz * dz;
            float nd = fminf(dist[j], d);
            dist[j] = nd;
            if (nd > bv) { bv = nd; bi = base + t + j * FPS_THREADS; }
        }
        // warp argmax (tie -> lower global idx)
#pragma unroll
        for (int off = 16; off; off >>= 1) {
            float ov = __shfl_down_sync(0xffffffffu, bv, off);
            int oi = __shfl_down_sync(0xffffffffu, bi, off);
            if (ov > bv || (ov == bv && oi < bi)) { bv = ov; bi = oi; }
        }
        if ((t & 31) == 0) { swv[t >> 5] = bv; swi[t >> 5] = bi; }
        __syncthreads();
        if (t < 16) {
            bv = swv[t]; bi = swi[t];
#pragma unroll
            for (int off = 8; off; off >>= 1) {
                float ov = __shfl_down_sync(0x0000ffffu, bv, off);
                int oi = __shfl_down_sync(0x0000ffffu, bi, off);
                if (ov > bv || (ov == bv && oi < bi)) { bv = ov; bi = oi; }
            }
            if (t == 0) {
                // push our CTA's candidate {coords, val, idx} to slot[rank]
                // of every CTA in the cluster (double-buffered by parity).
                int li = bi - base;
                float fx = sx[li], fy = sy[li], fz = sz[li];
                unsigned buf = (unsigned)(g & 1);
                unsigned la4 = smem_u32(&cand[buf][rank]);
                unsigned lai = smem_u32(&candi[buf][rank]);
#pragma unroll
                for (unsigned r = 0; r < FPS_CTAS; r++) {
                    unsigned ra4 = mapa_u32(la4, r);
                    unsigned rai = mapa_u32(lai, r);
                    asm volatile(
                        "st.shared::cluster.v4.f32 [%0], {%1, %2, %3, %4};"
                        :: "r"(ra4), "f"(fx), "f"(fy), "f"(fz), "f"(bv)
                        : "memory");
                    asm volatile(
                        "st.shared::cluster.u32 [%0], %1;"
                        :: "r"(rai), "r"(bi) : "memory");
                }
            }
        }
        asm volatile("barrier.cluster.arrive.aligned;" ::: "memory");
        asm volatile("barrier.cluster.wait.aligned;" ::: "memory");

        // combine 4 candidates (every thread, local SMEM broadcast)
        {
            unsigned buf = (unsigned)(g & 1);
            float nv = -1.0f, nx = 0.f, ny = 0.f, nz = 0.f;
            int ni = 0x7fffffff;
#pragma unroll
            for (int r = 0; r < FPS_CTAS; r++) {
                float4 c4 = cand[buf][r];
                int ci = candi[buf][r];
                if (c4.w > nv || (c4.w == nv && ci < ni)) {
                    nv = c4.w; ni = ci; nx = c4.x; ny = c4.y; nz = c4.z;
                }
            }
            cx = nx; cy = ny; cz = nz;
        }
    }
}

// ---------------------------------------------------------------------------
// group_kernel helpers
// ---------------------------------------------------------------------------
__device__ __forceinline__ unsigned dist_key(float x, float y, float z,
                                             float cx, float cy, float cz,
                                             float c2) {
    float p2 = x * x + y * y + z * z;
    float dot = cx * x + cy * y + cz * z;
    float f = (c2 + p2) - 2.0f * dot;
    unsigned u = __float_as_uint(f);
    return (u & 0x80000000u) ? ~u : (u | 0x80000000u);
}

// Parallel 256-bin cumulative search: finds the bin containing the k-th key.
// Replaces the serial t==0 scan. Exactly one thread writes the result.
__device__ __forceinline__ void select_bin(unsigned* hist, unsigned* wsum,
                                           unsigned* s_prefix, int* s_k,
                                           unsigned prefix, int k, int shift,
                                           int t, int lane) {
    unsigned x = 0, c = 0;
    if (t < 256) {
        c = hist[t];
        x = c;
#pragma unroll
        for (int off = 1; off < 32; off <<= 1) {
            unsigned y = __shfl_up_sync(0xffffffffu, x, off);
            if (lane >= off) x += y;
        }
        if (lane == 31) wsum[t >> 5] = x;
    }
    __syncthreads();
    if (t < 8) {
        unsigned v = wsum[t];
        unsigned xx = v;
#pragma unroll
        for (int off = 1; off < 8; off <<= 1) {
            unsigned y = __shfl_up_sync(0x000000ffu, xx, off);
            if (t >= off) xx += y;
        }
        wsum[t] = xx - v;  // exclusive
    }
    __syncthreads();
    if (t < 256) {
        unsigned incl = x + wsum[t >> 5];
        unsigned excl = incl - c;
        if (excl < (unsigned)k && incl >= (unsigned)k) {
            *s_prefix = prefix | ((unsigned)t << shift);
            *s_k = k - (int)excl;
        }
    }
    __syncthreads();
}

// ---------------------------------------------------------------------------
// Kernel 2: per-(b,g) exact top-64 smallest dist2 (radix select with stable
// lax.top_k tie semantics), then fused gelu-MLP layer 1 + mean over 64
// neighbors. 512 threads. Key-gen fused into round-1 histogram; round-1
// atomics warp-aggregated via match_any; parallel bin scans; float4/uint4 IO.
// ---------------------------------------------------------------------------
__global__ __launch_bounds__(512) void group_kernel(const float* __restrict__ pts,
                                                    const float* __restrict__ w1,
                                                    const float* __restrict__ b1) {
    extern __shared__ unsigned char dyn_smem[];
    unsigned* s_keys = reinterpret_cast<unsigned*>(dyn_smem);  // [NPTS]
    uint4* s_keys4 = reinterpret_cast<uint4*>(dyn_smem);

    __shared__ unsigned hist[256];
    __shared__ unsigned wsum[8];
    __shared__ unsigned s_prefix;
    __shared__ int s_k;
    __shared__ int sel[KNN];
    __shared__ int eql[KNN];
    __shared__ int s_nless, s_neq;
    __shared__ float loc[KNN][3];
    __shared__ float hpart[512];

    const int g = blockIdx.x;
    const int b = blockIdx.y;
    const int t = threadIdx.x;
    const int lane = t & 31;

    const float* P = pts + (size_t)b * NPTS * 3;
    const float* C = g_cent + ((size_t)b * GRP + g) * 3;
    const float cx = C[0], cy = C[1], cz = C[2];
    const float c2 = cx * cx + cy * cy + cz * cz;

    // Pass 1: compute keys (float4 loads, uint4 stores) + round-1 histogram
    // with match_any-aggregated atomics (distance bins cluster heavily).
    if (t < 256) hist[t] = 0;
    __syncthreads();
    const float4* P4 = reinterpret_cast<const float4*>(P);
    for (int c = t; c < NPTS / 4; c += 512) {
        float4 a = P4[3 * c + 0];
        float4 q = P4[3 * c + 1];
        float4 r = P4[3 * c + 2];
        unsigned k0 = dist_key(a.x, a.y, a.z, cx, cy, cz, c2);
        unsigned k1 = dist_key(a.w, q.x, q.y, cx, cy, cz, c2);
        unsigned k2 = dist_key(q.z, q.w, r.x, cx, cy, cz, c2);
        unsigned k3 = dist_key(r.y, r.z, r.w, cx, cy, cz, c2);
        s_keys4[c] = make_uint4(k0, k1, k2, k3);
        unsigned kk[4] = {k0, k1, k2, k3};
#pragma unroll
        for (int e = 0; e < 4; e++) {
            unsigned bin = kk[e] >> 24;
            unsigned peers = __match_any_sync(0xffffffffu, bin);
            if (lane == __ffs(peers) - 1)
                atomicAdd(&hist[bin], (unsigned)__popc(peers));
        }
    }
    __syncthreads();

    select_bin(hist, wsum, &s_prefix, &s_k, 0u, KNN, 24, t, lane);
    unsigned prefix = s_prefix;
    int k = s_k;

    // Rounds 2-4: only keys matching the running prefix hit the histogram
    // (few), so plain atomics are fine; the scan itself is uint4 LDS.
#pragma unroll
    for (int shift = 16; shift >= 0; shift -= 8) {
        if (t < 256) hist[t] = 0;
        __syncthreads();
        const unsigned hmask = 0xFFFFFFFFu << (shift + 8);
        for (int c = t; c < NPTS / 4; c += 512) {
            uint4 kk = s_keys4[c];
            if ((kk.x & hmask) == prefix) atomicAdd(&hist[(kk.x >> shift) & 255u], 1u);
            if ((kk.y & hmask) == prefix) atomicAdd(&hist[(kk.y >> shift) & 255u], 1u);
            if ((kk.z & hmask) == prefix) atomicAdd(&hist[(kk.z >> shift) & 255u], 1u);
            if ((kk.w & hmask) == prefix) atomicAdd(&hist[(kk.w >> shift) & 255u], 1u);
        }
        __syncthreads();
        select_bin(hist, wsum, &s_prefix, &s_k, prefix, k, shift, t, lane);
        prefix = s_prefix;
        k = s_k;
    }
    const unsigned T = prefix;

    // gather: all keys < T, then lowest-index ties == T
    if (t == 0) { s_nless = 0; s_neq = 0; }
    __syncthreads();
    for (int c = t; c < NPTS / 4; c += 512) {
        uint4 kk = s_keys4[c];
        unsigned kv[4] = {kk.x, kk.y, kk.z, kk.w};
#pragma unroll
        for (int e = 0; e < 4; e++) {
            if (kv[e] < T) {
                int p = atomicAdd(&s_nless, 1);
                sel[p] = 4 * c + e;
            } else if (kv[e] == T) {
                int p = atomicAdd(&s_neq, 1);
                if (p < KNN) eql[p] = 4 * c + e;
            }
        }
    }
    __syncthreads();
    if (t == 0) {
        int nless = s_nless;
        int need = KNN - nless;
        int m = (s_neq < KNN) ? s_neq : KNN;
        for (int a = 1; a < m; a++) {  // insertion sort (tiny)
            int v = eql[a];
            int c = a - 1;
            while (c >= 0 && eql[c] > v) { eql[c + 1] = eql[c]; c--; }
            eql[c + 1] = v;
        }
        for (int a = 0; a < need; a++) sel[nless + a] = eql[a];
    }
    __syncthreads();

    if (t < KNN) {
        int idx = sel[t];
        loc[t][0] = P[idx * 3 + 0] - cx;
        loc[t][1] = P[idx * 3 + 1] - cy;
        loc[t][2] = P[idx * 3 + 2] - cz;
    }
    __syncthreads();

    // hbar[j] = mean_k gelu(loc_k . w1[:,j] + b1[j]); exact-erf gelu.
    // 512 threads: (j = t&127) x (quarter of k).
    const int j = t & 127;
    const float wx = w1[j], wy = w1[HID + j], wz = w1[2 * HID + j], bb = b1[j];
    float acc = 0.0f;
    const int k0 = (t >> 7) * 16;
#pragma unroll
    for (int kk = 0; kk < 16; kk++) {
        int kp = k0 + kk;
        float v = loc[kp][0] * wx + loc[kp][1] * wy + loc[kp][2] * wz + bb;
        float h = 0.5f * v * (1.0f + erff(v * 0.7071067811865476f));
        acc += h;
    }
    hpart[t] = acc;
    __syncthreads();
    if (t < HID)
        g_hbar[((size_t)b * GRP + g) * HID + t] =
            (hpart[t] + hpart[t + 128] + hpart[t + 256] + hpart[t + 384]) *
            (1.0f / (float)KNN);
}

// ---------------------------------------------------------------------------
// Kernel 3: tokens = hbar @ w2 + b2 (4096x384x128 GEMM), then LayerNorm.
// 16 rows per block, 384 threads (one output column each).
// ---------------------------------------------------------------------------
__global__ __launch_bounds__(384) void head_kernel(const float* __restrict__ w2,
                                                   const float* __restrict__ b2,
                                                   const float* __restrict__ gamma,
                                                   const float* __restrict__ beta,
                                                   float* __restrict__ out_tok) {
    __shared__ float sh[16 * HID];
    __shared__ float tok[16][DIM];

    const int row0 = blockIdx.x * 16;
    const int t = threadIdx.x;

    for (int i = t; i < 16 * HID; i += 384)
        sh[i] = g_hbar[(size_t)row0 * HID + i];
    __syncthreads();

    float acc[16];
#pragma unroll
    for (int r = 0; r < 16; r++) acc[r] = 0.0f;

    for (int jj = 0; jj < HID; jj++) {
        float w = w2[jj * DIM + t];
#pragma unroll
        for (int r = 0; r < 16; r++) acc[r] += sh[r * HID + jj] * w;
    }
    const float bd = b2[t];
#pragma unroll
    for (int r = 0; r < 16; r++) tok[r][t] = acc[r] + bd;
    __syncthreads();

    const int w = t >> 5, lane = t & 31;
    for (int r = w; r < 16; r += 12) {
        float s = 0.0f;
        for (int c = lane; c < DIM; c += 32) s += tok[r][c];
#pragma unroll
        for (int off = 16; off; off >>= 1) s += __shfl_xor_sync(0xffffffffu, s, off);
        float mu = s * (1.0f / DIM);
        float v = 0.0f;
        for (int c = lane; c < DIM; c += 32) {
            float d0 = tok[r][c] - mu;
            v += d0 * d0;
        }
#pragma unroll
        for (int off = 16; off; off >>= 1) v += __shfl_xor_sync(0xffffffffu, v, off);
        float rstd = rsqrtf(v * (1.0f / DIM) + 1e-5f);
        for (int c = lane; c < DIM; c += 32)
            out_tok[((size_t)row0 + r) * DIM + c] =
                (tok[r][c] - mu) * rstd * gamma[c] + beta[c];
    }
}

// ---------------------------------------------------------------------------
extern "C" void kernel_launch(void* const* d_in, const int* in_sizes, int n_in,
                              void* d_out, int out_size) {
    const float* pts   = (const float*)d_in[0];  // [32,16384,3]
    const float* w1    = (const float*)d_in[1];  // [3,128]
    const float* b1    = (const float*)d_in[2];  // [128]
    const float* w2    = (const float*)d_in[3];  // [128,384]
    const float* b2    = (const float*)d_in[4];  // [384]
    const float* gamma = (const float*)d_in[5];  // [384]
    const float* beta  = (const float*)d_in[6];  // [384]

    float* out = (float*)d_out;
    float* out_cent = nullptr;
    float* out_tok = out;
    if (out_size == BATCH * GRP * (3 + DIM)) {
        out_cent = out;
        out_tok = out + BATCH * GRP * 3;
    }

    cudaFuncSetAttribute(fps_kernel, cudaFuncAttributeMaxDynamicSharedMemorySize,
                         3 * FPS_PTS * (int)sizeof(float));
    cudaFuncSetAttribute(group_kernel, cudaFuncAttributeMaxDynamicSharedMemorySize,
                         NPTS * (int)sizeof(unsigned));

    fps_kernel<<<BATCH * FPS_CTAS, FPS_THREADS, 3 * FPS_PTS * sizeof(float)>>>(pts, out_cent);
    group_kernel<<<dim3(GRP, BATCH), 512, NPTS * sizeof(unsigned)>>>(pts, w1, b1);
    head_kernel<<<(BATCH * GRP) / 16, 384>>>(w2, b2, gamma, beta, out_tok);
}

// round 15
// speedup vs baseline: 1.1945x; 1.0495x over previous
#include <cuda_runtime.h>

#define BATCH 32
#define NPTS  16384
#define GRP   128
#define KNN   64
#define HID   128
#define DIM   384

#define FPS_CTAS    4
#define FPS_THREADS 512
#define FPS_PTS     (NPTS / FPS_CTAS)        // 4096
#define FPS_PPT     (FPS_PTS / FPS_THREADS)  // 8

// Scratch (no allocations allowed)
__device__ float g_cent[BATCH * GRP * 3];
__device__ float g_hbar[BATCH * GRP * HID];

__device__ __forceinline__ unsigned smem_u32(const void* p) {
    return (unsigned)__cvta_generic_to_shared(p);
}
__device__ __forceinline__ unsigned cluster_rank() {
    unsigned r;
    asm("mov.u32 %0, %%cluster_ctarank;" : "=r"(r));
    return r;
}
__device__ __forceinline__ unsigned mapa_u32(unsigned addr, unsigned rank) {
    unsigned r;
    asm("mapa.shared::cluster.u32 %0, %1, %2;" : "=r"(r) : "r"(addr), "r"(rank));
    return r;
}
// Acquire-cluster parity wait on a local mbarrier.
__device__ __forceinline__ void mbar_wait_cluster(unsigned addr, unsigned parity) {
    asm volatile(
        "{\n\t"
        ".reg .pred P;\n\t"
        "WL_%=:\n\t"
        "mbarrier.try_wait.parity.acquire.cluster.shared::cta.b64 P, [%0], %1, 0x989680;\n\t"
        "@!P bra WL_%=;\n\t"
        "}" :: "r"(addr), "r"(parity) : "memory");
}

// ---------------------------------------------------------------------------
// Kernel 1: Farthest point sampling, 4-CTA cluster per batch.
// Each CTA owns 4096 points (8/thread in registers; coords mirrored in SMEM
// for winner lookup). Per round:
//   - per-thread dist update + best (exact (p-c)^2 sub/fma form)
//   - packed-u64 (dist_bits<<32 | ~idx) atomicMax into per-warp slot
//   - warp0 reduces 16 slots, leader pushes {pack, coords} to all 4 CTAs'
//     double-buffered slots via DSMEM stores + release-cluster mbarrier
//     arrive; consumers acquire-cluster parity-wait (no barrier.cluster).
// Winner = (max dist, lowest global idx) — identical to reference argmax.
// ---------------------------------------------------------------------------
__global__ __launch_bounds__(FPS_THREADS) __cluster_dims__(FPS_CTAS, 1, 1)
void fps_kernel(const float* __restrict__ pts, float* __restrict__ out_cent) {
    extern __shared__ unsigned char dsm[];
    float* sx = reinterpret_cast<float*>(dsm);       // [4096]
    float* sy = sx + FPS_PTS;
    float* sz = sy + FPS_PTS;
    __shared__ unsigned long long warp_best[16];
    __shared__ unsigned long long cand_pack[2][FPS_CTAS];
    __shared__ float4 cand_xyz[2][FPS_CTAS];
    __shared__ unsigned long long mbar;

    const unsigned rank = cluster_rank();
    const int b = blockIdx.x / FPS_CTAS;
    const int t = threadIdx.x;
    const float* P = pts + (size_t)b * NPTS * 3;
    const int base = (int)rank * FPS_PTS;

    float px[FPS_PPT], py[FPS_PPT], pz[FPS_PPT], dist[FPS_PPT];
#pragma unroll
    for (int j = 0; j < FPS_PPT; j++) {
        int idx = t + j * FPS_THREADS;
        int gi = base + idx;
        px[j] = P[gi * 3 + 0];
        py[j] = P[gi * 3 + 1];
        pz[j] = P[gi * 3 + 2];
        sx[idx] = px[j]; sy[idx] = py[j]; sz[idx] = pz[j];
        dist[j] = 3.4e38f;
    }
    if (t < 16) warp_best[t] = 0ull;
    if (t == 0) {
        unsigned m = smem_u32(&mbar);
        asm volatile("mbarrier.init.shared.b64 [%0], %1;"
                     :: "r"(m), "r"((unsigned)FPS_CTAS) : "memory");
    }
    __syncthreads();
    // all peers' mbarriers must be live before any remote arrive
    asm volatile("barrier.cluster.arrive.aligned;" ::: "memory");
    asm volatile("barrier.cluster.wait.aligned;" ::: "memory");

    // start: farthest = index 0; every CTA reads its coords from L2.
    float cx = P[0], cy = P[1], cz = P[2];

    for (int g = 0; g < GRP; g++) {
        if (rank == 0 && t == 0) {
            size_t o = ((size_t)b * GRP + g) * 3;
            g_cent[o + 0] = cx; g_cent[o + 1] = cy; g_cent[o + 2] = cz;
            if (out_cent) {
                out_cent[o + 0] = cx; out_cent[o + 1] = cy; out_cent[o + 2] = cz;
            }
        }

        // per-thread best (value desc, global idx asc within thread)
        float bv = -1.0f;
        int bi = 0;
#pragma unroll
        for (int j = 0; j < FPS_PPT; j++) {
            float dx = px[j] - cx;
            float dy = py[j] - cy;
            float dz = pz[j] - cz;
            float d = dx * dx + dy * dy + dz * dz;
            float nd = fminf(dist[j], d);
            dist[j] = nd;
            if (nd > bv) { bv = nd; bi = base + t + j * FPS_THREADS; }
        }
        // pack: dist bits (nonneg float -> orderable) | inverted idx (tie->low)
        unsigned long long pack =
            ((unsigned long long)__float_as_uint(bv) << 32) |
            (unsigned long long)(0xFFFFFFFFu - (unsigned)bi);
        atomicMax(&warp_best[t >> 5], pack);
        __syncthreads();

        if (t < 32) {
            unsigned long long v = (t < 16) ? warp_best[t] : 0ull;
            if (t < 16) warp_best[t] = 0ull;  // reset for next round
            __syncwarp();
#pragma unroll
            for (int off = 8; off; off >>= 1) {
                unsigned long long ov = __shfl_down_sync(0xffffffffu, v, off);
                if (ov > v) v = ov;
            }
            if (t == 0) {
                int gi = (int)(0xFFFFFFFFu - (unsigned)(v & 0xFFFFFFFFull));
                int li = gi - base;
                float fx = sx[li], fy = sy[li], fz = sz[li];
                unsigned buf = (unsigned)(g & 1);
                unsigned lp = smem_u32(&cand_pack[buf][rank]);
                unsigned lx = smem_u32(&cand_xyz[buf][rank]);
                unsigned lm = smem_u32(&mbar);
#pragma unroll
                for (unsigned r = 0; r < FPS_CTAS; r++) {
                    unsigned rp = mapa_u32(lp, r);
                    unsigned rx = mapa_u32(lx, r);
                    unsigned rm = mapa_u32(lm, r);
                    asm volatile("st.shared::cluster.u64 [%0], %1;"
                                 :: "r"(rp), "l"(v) : "memory");
                    asm volatile("st.shared::cluster.v4.f32 [%0], {%1, %2, %3, %4};"
                                 :: "r"(rx), "f"(fx), "f"(fy), "f"(fz), "f"(0.0f)
                                 : "memory");
                    asm volatile(
                        "mbarrier.arrive.release.cluster.shared::cluster.b64 _, [%0];"
                        :: "r"(rm) : "memory");
                }
            }
        }

        // wait for all 4 candidates of this round, then combine locally
        mbar_wait_cluster(smem_u32(&mbar), (unsigned)(g & 1));
        {
            unsigned buf = (unsigned)(g & 1);
            unsigned long long best = cand_pack[buf][0];
            int br = 0;
#pragma unroll
            for (int r = 1; r < FPS_CTAS; r++) {
                unsigned long long c = cand_pack[buf][r];
                if (c > best) { best = c; br = r; }
            }
            float4 w = cand_xyz[buf][br];
            cx = w.x; cy = w.y; cz = w.z;
        }
    }

    // keep SMEM alive until all peers are done with remote ops
    asm volatile("barrier.cluster.arrive.aligned;" ::: "memory");
    asm volatile("barrier.cluster.wait.aligned;" ::: "memory");
}

// ---------------------------------------------------------------------------
// group_kernel helpers
// ---------------------------------------------------------------------------
__device__ __forceinline__ unsigned dist_key(float x, float y, float z,
                                             float cx, float cy, float cz,
                                             float c2) {
    float p2 = x * x + y * y + z * z;
    float dot = cx * x + cy * y + cz * z;
    float f = (c2 + p2) - 2.0f * dot;
    unsigned u = __float_as_uint(f);
    return (u & 0x80000000u) ? ~u : (u | 0x80000000u);
}

// Parallel 256-bin cumulative search: finds the bin containing the k-th key.
__device__ __forceinline__ void select_bin(unsigned* hist, unsigned* wsum,
                                           unsigned* s_prefix, int* s_k,
                                           unsigned prefix, int k, int shift,
                                           int t, int lane) {
    unsigned x = 0, c = 0;
    if (t < 256) {
        c = hist[t];
        x = c;
#pragma unroll
        for (int off = 1; off < 32; off <<= 1) {
            unsigned y = __shfl_up_sync(0xffffffffu, x, off);
            if (lane >= off) x += y;
        }
        if (lane == 31) wsum[t >> 5] = x;
    }
    __syncthreads();
    if (t < 8) {
        unsigned v = wsum[t];
        unsigned xx = v;
#pragma unroll
        for (int off = 1; off < 8; off <<= 1) {
            unsigned y = __shfl_up_sync(0x000000ffu, xx, off);
            if (t >= off) xx += y;
        }
        wsum[t] = xx - v;  // exclusive
    }
    __syncthreads();
    if (t < 256) {
        unsigned incl = x + wsum[t >> 5];
        unsigned excl = incl - c;
        if (excl < (unsigned)k && incl >= (unsigned)k) {
            *s_prefix = prefix | ((unsigned)t << shift);
            *s_k = k - (int)excl;
        }
    }
    __syncthreads();
}

// ---------------------------------------------------------------------------
// Kernel 2: per-(b,g) exact top-64 smallest dist2 (radix select with stable
// lax.top_k tie semantics), then fused gelu-MLP layer 1 + mean over 64
// neighbors. 512 threads. Key-gen fused into round-1 histogram; round-1
// atomics warp-aggregated via match_any; parallel bin scans; float4/uint4 IO.
// ---------------------------------------------------------------------------
__global__ __launch_bounds__(512) void group_kernel(const float* __restrict__ pts,
                                                    const float* __restrict__ w1,
                                                    const float* __restrict__ b1) {
    extern __shared__ unsigned char dyn_smem[];
    uint4* s_keys4 = reinterpret_cast<uint4*>(dyn_smem);  // [NPTS/4]

    __shared__ unsigned hist[256];
    __shared__ unsigned wsum[8];
    __shared__ unsigned s_prefix;
    __shared__ int s_k;
    __shared__ int sel[KNN];
    __shared__ int eql[KNN];
    __shared__ int s_nless, s_neq;
    __shared__ float loc[KNN][3];
    __shared__ float hpart[512];

    const int g = blockIdx.x;
    const int b = blockIdx.y;
    const int t = threadIdx.x;
    const int lane = t & 31;

    const float* P = pts + (size_t)b * NPTS * 3;
    const float* C = g_cent + ((size_t)b * GRP + g) * 3;
    const float cx = C[0], cy = C[1], cz = C[2];
    const float c2 = cx * cx + cy * cy + cz * cz;

    if (t < 256) hist[t] = 0;
    __syncthreads();
    const float4* P4 = reinterpret_cast<const float4*>(P);
    for (int c = t; c < NPTS / 4; c += 512) {
        float4 a = P4[3 * c + 0];
        float4 q = P4[3 * c + 1];
        float4 r = P4[3 * c + 2];
        unsigned k0 = dist_key(a.x, a.y, a.z, cx, cy, cz, c2);
        unsigned k1 = dist_key(a.w, q.x, q.y, cx, cy, cz, c2);
        unsigned k2 = dist_key(q.z, q.w, r.x, cx, cy, cz, c2);
        unsigned k3 = dist_key(r.y, r.z, r.w, cx, cy, cz, c2);
        s_keys4[c] = make_uint4(k0, k1, k2, k3);
        unsigned kk[4] = {k0, k1, k2, k3};
#pragma unroll
        for (int e = 0; e < 4; e++) {
            unsigned bin = kk[e] >> 24;
            unsigned peers = __match_any_sync(0xffffffffu, bin);
            if (lane == __ffs(peers) - 1)
                atomicAdd(&hist[bin], (unsigned)__popc(peers));
        }
    }
    __syncthreads();

    select_bin(hist, wsum, &s_prefix, &s_k, 0u, KNN, 24, t, lane);
    unsigned prefix = s_prefix;
    int k = s_k;

#pragma unroll
    for (int shift = 16; shift >= 0; shift -= 8) {
        if (t < 256) hist[t] = 0;
        __syncthreads();
        const unsigned hmask = 0xFFFFFFFFu << (shift + 8);
        for (int c = t; c < NPTS / 4; c += 512) {
            uint4 kk = s_keys4[c];
            if ((kk.x & hmask) == prefix) atomicAdd(&hist[(kk.x >> shift) & 255u], 1u);
            if ((kk.y & hmask) == prefix) atomicAdd(&hist[(kk.y >> shift) & 255u], 1u);
            if ((kk.z & hmask) == prefix) atomicAdd(&hist[(kk.z >> shift) & 255u], 1u);
            if ((kk.w & hmask) == prefix) atomicAdd(&hist[(kk.w >> shift) & 255u], 1u);
        }
        __syncthreads();
        select_bin(hist, wsum, &s_prefix, &s_k, prefix, k, shift, t, lane);
        prefix = s_prefix;
        k = s_k;
    }
    const unsigned T = prefix;

    // gather: all keys < T, then lowest-index ties == T
    if (t == 0) { s_nless = 0; s_neq = 0; }
    __syncthreads();
    for (int c = t; c < NPTS / 4; c += 512) {
        uint4 kk = s_keys4[c];
        unsigned kv[4] = {kk.x, kk.y, kk.z, kk.w};
#pragma unroll
        for (int e = 0; e < 4; e++) {
            if (kv[e] < T) {
                int p = atomicAdd(&s_nless, 1);
                sel[p] = 4 * c + e;
            } else if (kv[e] == T) {
                int p = atomicAdd(&s_neq, 1);
                if (p < KNN) eql[p] = 4 * c + e;
            }
        }
    }
    __syncthreads();
    if (t == 0) {
        int nless = s_nless;
        int need = KNN - nless;
        int m = (s_neq < KNN) ? s_neq : KNN;
        for (int a = 1; a < m; a++) {  // insertion sort (tiny)
            int v = eql[a];
            int c = a - 1;
            while (c >= 0 && eql[c] > v) { eql[c + 1] = eql[c]; c--; }
            eql[c + 1] = v;
        }
        for (int a = 0; a < need; a++) sel[nless + a] = eql[a];
    }
    __syncthreads();

    if (t < KNN) {
        int idx = sel[t];
        loc[t][0] = P[idx * 3 + 0] - cx;
        loc[t][1] = P[idx * 3 + 1] - cy;
        loc[t][2] = P[idx * 3 + 2] - cz;
    }
    __syncthreads();

    // hbar[j] = mean_k gelu(loc_k . w1[:,j] + b1[j]); exact-erf gelu.
    const int j = t & 127;
    const float wx = w1[j], wy = w1[HID + j], wz = w1[2 * HID + j], bb = b1[j];
    float acc = 0.0f;
    const int k0 = (t >> 7) * 16;
#pragma unroll
    for (int kk = 0; kk < 16; kk++) {
        int kp = k0 + kk;
        float v = loc[kp][0] * wx + loc[kp][1] * wy + loc[kp][2] * wz + bb;
        float h = 0.5f * v * (1.0f + erff(v * 0.7071067811865476f));
        acc += h;
    }
    hpart[t] = acc;
    __syncthreads();
    if (t < HID)
        g_hbar[((size_t)b * GRP + g) * HID + t] =
            (hpart[t] + hpart[t + 128] + hpart[t + 256] + hpart[t + 384]) *
            (1.0f / (float)KNN);
}

// ---------------------------------------------------------------------------
// Kernel 3: tokens = hbar @ w2 + b2 (4096x384x128 GEMM), then LayerNorm.
// ---------------------------------------------------------------------------
__global__ __launch_bounds__(384) void head_kernel(const float* __restrict__ w2,
                                                   const float* __restrict__ b2,
                                                   const float* __restrict__ gamma,
                                                   const float* __restrict__ beta,
                                                   float* __restrict__ out_tok) {
    __shared__ float sh[16 * HID];
    __shared__ float tok[16][DIM];

    const int row0 = blockIdx.x * 16;
    const int t = threadIdx.x;

    for (int i = t; i < 16 * HID; i += 384)
        sh[i] = g_hbar[(size_t)row0 * HID + i];
    __syncthreads();

    float acc[16];
#pragma unroll
    for (int r = 0; r < 16; r++) acc[r] = 0.0f;

    for (int jj = 0; jj < HID; jj++) {
        float w = w2[jj * DIM + t];
#pragma unroll
        for (int r = 0; r < 16; r++) acc[r] += sh[r * HID + jj] * w;
    }
    const float bd = b2[t];
#pragma unroll
    for (int r = 0; r < 16; r++) tok[r][t] = acc[r] + bd;
    __syncthreads();

    const int w = t >> 5, lane = t & 31;
    for (int r = w; r < 16; r += 12) {
        float s = 0.0f;
        for (int c = lane; c < DIM; c += 32) s += tok[r][c];
#pragma unroll
        for (int off = 16; off; off >>= 1) s += __shfl_xor_sync(0xffffffffu, s, off);
        float mu = s * (1.0f / DIM);
        float v = 0.0f;
        for (int c = lane; c < DIM; c += 32) {
            float d0 = tok[r][c] - mu;
            v += d0 * d0;
        }
#pragma unroll
        for (int off = 16; off; off >>= 1) v += __shfl_xor_sync(0xffffffffu, v, off);
        float rstd = rsqrtf(v * (1.0f / DIM) + 1e-5f);
        for (int c = lane; c < DIM; c += 32)
            out_tok[((size_t)row0 + r) * DIM + c] =
                (tok[r][c] - mu) * rstd * gamma[c] + beta[c];
    }
}

// ---------------------------------------------------------------------------
extern "C" void kernel_launch(void* const* d_in, const int* in_sizes, int n_in,
                              void* d_out, int out_size) {
    const float* pts   = (const float*)d_in[0];  // [32,16384,3]
    const float* w1    = (const float*)d_in[1];  // [3,128]
    const float* b1    = (const float*)d_in[2];  // [128]
    const float* w2    = (const float*)d_in[3];  // [128,384]
    const float* b2    = (const float*)d_in[4];  // [384]
    const float* gamma = (const float*)d_in[5];  // [384]
    const float* beta  = (const float*)d_in[6];  // [384]

    float* out = (float*)d_out;
    float* out_cent = nullptr;
    float* out_tok = out;
    if (out_size == BATCH * GRP * (3 + DIM)) {
        out_cent = out;
        out_tok = out + BATCH * GRP * 3;
    }

    cudaFuncSetAttribute(fps_kernel, cudaFuncAttributeMaxDynamicSharedMemorySize,
                         3 * FPS_PTS * (int)sizeof(float));
    cudaFuncSetAttribute(group_kernel, cudaFuncAttributeMaxDynamicSharedMemorySize,
                         NPTS * (int)sizeof(unsigned));

    fps_kernel<<<BATCH * FPS_CTAS, FPS_THREADS, 3 * FPS_PTS * sizeof(float)>>>(pts, out_cent);
    group_kernel<<<dim3(GRP, BATCH), 512, NPTS * sizeof(unsigned)>>>(pts, w1, b1);
    head_kernel<<<(BATCH * GRP) / 16, 384>>>(w2, b2, gamma, beta, out_tok);
}

// round 16
// speedup vs baseline: 1.1980x; 1.0029x over previous
#include <cuda_runtime.h>

#define BATCH 32
#define NPTS  16384
#define GRP   128
#define KNN   64
#define HID   128
#define DIM   384

#define FPS_CTAS    4
#define FPS_THREADS 512
#define FPS_PTS     (NPTS / FPS_CTAS)        // 4096
#define FPS_PPT     (FPS_PTS / FPS_THREADS)  // 8

// Scratch (no allocations allowed)
__device__ float g_cent[BATCH * GRP * 3];
__device__ float g_hbar[BATCH * GRP * HID];

__device__ __forceinline__ unsigned smem_u32(const void* p) {
    return (unsigned)__cvta_generic_to_shared(p);
}
__device__ __forceinline__ unsigned cluster_rank() {
    unsigned r;
    asm("mov.u32 %0, %%cluster_ctarank;" : "=r"(r));
    return r;
}
__device__ __forceinline__ unsigned mapa_u32(unsigned addr, unsigned rank) {
    unsigned r;
    asm("mapa.shared::cluster.u32 %0, %1, %2;" : "=r"(r) : "r"(addr), "r"(rank));
    return r;
}
// Acquire-cluster parity wait on a local mbarrier.
__device__ __forceinline__ void mbar_wait_cluster(unsigned addr, unsigned parity) {
    asm volatile(
        "{\n\t"
        ".reg .pred P;\n\t"
        "WL_%=:\n\t"
        "mbarrier.try_wait.parity.acquire.cluster.shared::cta.b64 P, [%0], %1, 0x989680;\n\t"
        "@!P bra WL_%=;\n\t"
        "}" :: "r"(addr), "r"(parity) : "memory");
}

// ---------------------------------------------------------------------------
// Kernel 1: Farthest point sampling, 4-CTA cluster per batch.
// Each CTA owns 4096 points (8/thread in registers; coords mirrored in SMEM
// for winner lookup). Per round:
//   - per-thread dist update + best (exact (p-c)^2 sub/fma form)
//   - packed-u64 (dist_bits<<32 | ~idx) atomicMax into per-warp slot
//   - warp0 reduces 16 slots, leader pushes {pack, coords} to all 4 CTAs'
//     double-buffered slots via DSMEM stores + release-cluster mbarrier
//     arrive; consumers acquire-cluster parity-wait (no barrier.cluster).
// Winner = (max dist, lowest global idx) — identical to reference argmax.
// ---------------------------------------------------------------------------
__global__ __launch_bounds__(FPS_THREADS) __cluster_dims__(FPS_CTAS, 1, 1)
void fps_kernel(const float* __restrict__ pts, float* __restrict__ out_cent) {
    extern __shared__ unsigned char dsm[];
    float* sx = reinterpret_cast<float*>(dsm);       // [4096]
    float* sy = sx + FPS_PTS;
    float* sz = sy + FPS_PTS;
    __shared__ unsigned long long warp_best[16];
    __shared__ unsigned long long cand_pack[2][FPS_CTAS];
    __shared__ float4 cand_xyz[2][FPS_CTAS];
    __shared__ unsigned long long mbar;

    const unsigned rank = cluster_rank();
    const int b = blockIdx.x / FPS_CTAS;
    const int t = threadIdx.x;
    const float* P = pts + (size_t)b * NPTS * 3;
    const int base = (int)rank * FPS_PTS;

    float px[FPS_PPT], py[FPS_PPT], pz[FPS_PPT], dist[FPS_PPT];
#pragma unroll
    for (int j = 0; j < FPS_PPT; j++) {
        int idx = t + j * FPS_THREADS;
        int gi = base + idx;
        px[j] = P[gi * 3 + 0];
        py[j] = P[gi * 3 + 1];
        pz[j] = P[gi * 3 + 2];
        sx[idx] = px[j]; sy[idx] = py[j]; sz[idx] = pz[j];
        dist[j] = 3.4e38f;
    }
    if (t < 16) warp_best[t] = 0ull;
    if (t == 0) {
        unsigned m = smem_u32(&mbar);
        asm volatile("mbarrier.init.shared.b64 [%0], %1;"
                     :: "r"(m), "r"((unsigned)FPS_CTAS) : "memory");
    }
    __syncthreads();
    // all peers' mbarriers must be live before any remote arrive
    asm volatile("barrier.cluster.arrive.aligned;" ::: "memory");
    asm volatile("barrier.cluster.wait.aligned;" ::: "memory");

    // start: farthest = index 0; every CTA reads its coords from L2.
    float cx = P[0], cy = P[1], cz = P[2];

    for (int g = 0; g < GRP; g++) {
        if (rank == 0 && t == 0) {
            size_t o = ((size_t)b * GRP + g) * 3;
            g_cent[o + 0] = cx; g_cent[o + 1] = cy; g_cent[o + 2] = cz;
            if (out_cent) {
                out_cent[o + 0] = cx; out_cent[o + 1] = cy; out_cent[o + 2] = cz;
            }
        }

        // per-thread best (value desc, global idx asc within thread)
        float bv = -1.0f;
        int bi = 0;
#pragma unroll
        for (int j = 0; j < FPS_PPT; j++) {
            float dx = px[j] - cx;
            float dy = py[j] - cy;
            float dz = pz[j] - cz;
            float d = dx * dx + dy * dy + dz * dz;
            float nd = fminf(dist[j], d);
            dist[j] = nd;
            if (nd > bv) { bv = nd; bi = base + t + j * FPS_THREADS; }
        }
        // pack: dist bits (nonneg float -> orderable) | inverted idx (tie->low)
        unsigned long long pack =
            ((unsigned long long)__float_as_uint(bv) << 32) |
            (unsigned long long)(0xFFFFFFFFu - (unsigned)bi);
        atomicMax(&warp_best[t >> 5], pack);
        __syncthreads();

        if (t < 32) {
            unsigned long long v = (t < 16) ? warp_best[t] : 0ull;
            if (t < 16) warp_best[t] = 0ull;  // reset for next round
            __syncwarp();
#pragma unroll
            for (int off = 8; off; off >>= 1) {
                unsigned long long ov = __shfl_down_sync(0xffffffffu, v, off);
                if (ov > v) v = ov;
            }
            if (t == 0) {
                int gi = (int)(0xFFFFFFFFu - (unsigned)(v & 0xFFFFFFFFull));
                int li = gi - base;
                float fx = sx[li], fy = sy[li], fz = sz[li];
                unsigned buf = (unsigned)(g & 1);
                unsigned lp = smem_u32(&cand_pack[buf][rank]);
                unsigned lx = smem_u32(&cand_xyz[buf][rank]);
                unsigned lm = smem_u32(&mbar);
#pragma unroll
                for (unsigned r = 0; r < FPS_CTAS; r++) {
                    unsigned rp = mapa_u32(lp, r);
                    unsigned rx = mapa_u32(lx, r);
                    unsigned rm = mapa_u32(lm, r);
                    asm volatile("st.shared::cluster.u64 [%0], %1;"
                                 :: "r"(rp), "l"(v) : "memory");
                    asm volatile("st.shared::cluster.v4.f32 [%0], {%1, %2, %3, %4};"
                                 :: "r"(rx), "f"(fx), "f"(fy), "f"(fz), "f"(0.0f)
                                 : "memory");
                    asm volatile(
                        "mbarrier.arrive.release.cluster.shared::cluster.b64 _, [%0];"
                        :: "r"(rm) : "memory");
                }
            }
        }

        // wait for all 4 candidates of this round, then combine locally
        mbar_wait_cluster(smem_u32(&mbar), (unsigned)(g & 1));
        {
            unsigned buf = (unsigned)(g & 1);
            unsigned long long best = cand_pack[buf][0];
            int br = 0;
#pragma unroll
            for (int r = 1; r < FPS_CTAS; r++) {
                unsigned long long c = cand_pack[buf][r];
                if (c > best) { best = c; br = r; }
            }
            float4 w = cand_xyz[buf][br];
            cx = w.x; cy = w.y; cz = w.z;
        }
    }

    // keep SMEM alive until all peers are done with remote ops
    asm volatile("barrier.cluster.arrive.aligned;" ::: "memory");
    asm volatile("barrier.cluster.wait.aligned;" ::: "memory");
}

// ---------------------------------------------------------------------------
// group_kernel helpers
// ---------------------------------------------------------------------------
__device__ __forceinline__ unsigned dist_key(float x, float y, float z,
                                             float cx, float cy, float cz,
                                             float c2) {
    float p2 = x * x + y * y + z * z;
    float dot = cx * x + cy * y + cz * z;
    float f = (c2 + p2) - 2.0f * dot;
    unsigned u = __float_as_uint(f);
    return (u & 0x80000000u) ? ~u : (u | 0x80000000u);
}

// Parallel 256-bin cumulative search: finds the bin containing the k-th key.
__device__ __forceinline__ void select_bin(unsigned* hist, unsigned* wsum,
                                           unsigned* s_prefix, int* s_k,
                                           unsigned prefix, int k, int shift,
                                           int t, int lane) {
    unsigned x = 0, c = 0;
    if (t < 256) {
        c = hist[t];
        x = c;
#pragma unroll
        for (int off = 1; off < 32; off <<= 1) {
            unsigned y = __shfl_up_sync(0xffffffffu, x, off);
            if (lane >= off) x += y;
        }
        if (lane == 31) wsum[t >> 5] = x;
    }
    __syncthreads();
    if (t < 8) {
        unsigned v = wsum[t];
        unsigned xx = v;
#pragma unroll
        for (int off = 1; off < 8; off <<= 1) {
            unsigned y = __shfl_up_sync(0x000000ffu, xx, off);
            if (t >= off) xx += y;
        }
        wsum[t] = xx - v;  // exclusive
    }
    __syncthreads();
    if (t < 256) {
        unsigned incl = x + wsum[t >> 5];
        unsigned excl = incl - c;
        if (excl < (unsigned)k && incl >= (unsigned)k) {
            *s_prefix = prefix | ((unsigned)t << shift);
            *s_k = k - (int)excl;
        }
    }
    __syncthreads();
}

// ---------------------------------------------------------------------------
// Kernel 2: per-(b,g) exact top-64 smallest dist2 (radix select with stable
// lax.top_k tie semantics), then fused gelu-MLP layer 1 + mean over 64
// neighbors. 512 threads. Key-gen fused into round-1 histogram; round-1
// atomics warp-aggregated via match_any; parallel bin scans; float4/uint4 IO.
// ---------------------------------------------------------------------------
__global__ __launch_bounds__(512) void group_kernel(const float* __restrict__ pts,
                                                    const float* __restrict__ w1,
                                                    const float* __restrict__ b1) {
    extern __shared__ unsigned char dyn_smem[];
    uint4* s_keys4 = reinterpret_cast<uint4*>(dyn_smem);  // [NPTS/4]

    __shared__ unsigned hist[256];
    __shared__ unsigned wsum[8];
    __shared__ unsigned s_prefix;
    __shared__ int s_k;
    __shared__ int sel[KNN];
    __shared__ int eql[KNN];
    __shared__ int s_nless, s_neq;
    __shared__ float loc[KNN][3];
    __shared__ float hpart[512];

    const int g = blockIdx.x;
    const int b = blockIdx.y;
    const int t = threadIdx.x;
    const int lane = t & 31;

    const float* P = pts + (size_t)b * NPTS * 3;
    const float* C = g_cent + ((size_t)b * GRP + g) * 3;
    const float cx = C[0], cy = C[1], cz = C[2];
    const float c2 = cx * cx + cy * cy + cz * cz;

    if (t < 256) hist[t] = 0;
    __syncthreads();
    const float4* P4 = reinterpret_cast<const float4*>(P);
    for (int c = t; c < NPTS / 4; c += 512) {
        float4 a = P4[3 * c + 0];
        float4 q = P4[3 * c + 1];
        float4 r = P4[3 * c + 2];
        unsigned k0 = dist_key(a.x, a.y, a.z, cx, cy, cz, c2);
        unsigned k1 = dist_key(a.w, q.x, q.y, cx, cy, cz, c2);
        unsigned k2 = dist_key(q.z, q.w, r.x, cx, cy, cz, c2);
        unsigned k3 = dist_key(r.y, r.z, r.w, cx, cy, cz, c2);
        s_keys4[c] = make_uint4(k0, k1, k2, k3);
        unsigned kk[4] = {k0, k1, k2, k3};
#pragma unroll
        for (int e = 0; e < 4; e++) {
            unsigned bin = kk[e] >> 24;
            unsigned peers = __match_any_sync(0xffffffffu, bin);
            if (lane == __ffs(peers) - 1)
                atomicAdd(&hist[bin], (unsigned)__popc(peers));
        }
    }
    __syncthreads();

    select_bin(hist, wsum, &s_prefix, &s_k, 0u, KNN, 24, t, lane);
    unsigned prefix = s_prefix;
    int k = s_k;

#pragma unroll
    for (int shift = 16; shift >= 0; shift -= 8) {
        if (t < 256) hist[t] = 0;
        __syncthreads();
        const unsigned hmask = 0xFFFFFFFFu << (shift + 8);
        for (int c = t; c < NPTS / 4; c += 512) {
            uint4 kk = s_keys4[c];
            if ((kk.x & hmask) == prefix) atomicAdd(&hist[(kk.x >> shift) & 255u], 1u);
            if ((kk.y & hmask) == prefix) atomicAdd(&hist[(kk.y >> shift) & 255u], 1u);
            if ((kk.z & hmask) == prefix) atomicAdd(&hist[(kk.z >> shift) & 255u], 1u);
            if ((kk.w & hmask) == prefix) atomicAdd(&hist[(kk.w >> shift) & 255u], 1u);
        }
        __syncthreads();
        select_bin(hist, wsum, &s_prefix, &s_k, prefix, k, shift, t, lane);
        prefix = s_prefix;
        k = s_k;
    }
    const unsigned T = prefix;

    // gather: all keys < T, then lowest-index ties == T
    if (t == 0) { s_nless = 0; s_neq = 0; }
    __syncthreads();
    for (int c = t; c < NPTS / 4; c += 512) {
        uint4 kk = s_keys4[c];
        unsigned kv[4] = {kk.x, kk.y, kk.z, kk.w};
#pragma unroll
        for (int e = 0; e < 4; e++) {
            if (kv[e] < T) {
                int p = atomicAdd(&s_nless, 1);
                sel[p] = 4 * c + e;
            } else if (kv[e] == T) {
                int p = atomicAdd(&s_neq, 1);
                if (p < KNN) eql[p] = 4 * c + e;
            }
        }
    }
    __syncthreads();
    if (t == 0) {
        int nless = s_nless;
        int need = KNN - nless;
        int m = (s_neq < KNN) ? s_neq : KNN;
        for (int a = 1; a < m; a++) {  // insertion sort (tiny)
            int v = eql[a];
            int c = a - 1;
            while (c >= 0 && eql[c] > v) { eql[c + 1] = eql[c]; c--; }
            eql[c + 1] = v;
        }
        for (int a = 0; a < need; a++) sel[nless + a] = eql[a];
    }
    __syncthreads();

    if (t < KNN) {
        int idx = sel[t];
        loc[t][0] = P[idx * 3 + 0] - cx;
        loc[t][1] = P[idx * 3 + 1] - cy;
        loc[t][2] = P[idx * 3 + 2] - cz;
    }
    __syncthreads();

    // hbar[j] = mean_k gelu(loc_k . w1[:,j] + b1[j]); exact-erf gelu.
    const int j = t & 127;
    const float wx = w1[j], wy = w1[HID + j], wz = w1[2 * HID + j], bb = b1[j];
    float acc = 0.0f;
    const int k0 = (t >> 7) * 16;
#pragma unroll
    for (int kk = 0; kk < 16; kk++) {
        int kp = k0 + kk;
        float v = loc[kp][0] * wx + loc[kp][1] * wy + loc[kp][2] * wz + bb;
        float h = 0.5f * v * (1.0f + erff(v * 0.7071067811865476f));
        acc += h;
    }
    hpart[t] = acc;
    __syncthreads();
    if (t < HID)
        g_hbar[((size_t)b * GRP + g) * HID + t] =
            (hpart[t] + hpart[t + 128] + hpart[t + 256] + hpart[t + 384]) *
            (1.0f / (float)KNN);
}

// ---------------------------------------------------------------------------
// Kernel 3: tokens = hbar @ w2 + b2 (4096x384x128 GEMM), then LayerNorm.
// ---------------------------------------------------------------------------
__global__ __launch_bounds__(384) void head_kernel(const float* __restrict__ w2,
                                                   const float* __restrict__ b2,
                                                   const float* __restrict__ gamma,
                                                   const float* __restrict__ beta,
                                                   float* __restrict__ out_tok) {
    __shared__ float sh[16 * HID];
    __shared__ float tok[16][DIM];

    const int row0 = blockIdx.x * 16;
    const int t = threadIdx.x;

    for (int i = t; i < 16 * HID; i += 384)
        sh[i] = g_hbar[(size_t)row0 * HID + i];
    __syncthreads();

    float acc[16];
#pragma unroll
    for (int r = 0; r < 16; r++) acc[r] = 0.0f;

    for (int jj = 0; jj < HID; jj++) {
        float w = w2[jj * DIM + t];
#pragma unroll
        for (int r = 0; r < 16; r++) acc[r] += sh[r * HID + jj] * w;
    }
    const float bd = b2[t];
#pragma unroll
    for (int r = 0; r < 16; r++) tok[r][t] = acc[r] + bd;
    __syncthreads();

    const int w = t >> 5, lane = t & 31;
    for (int r = w; r < 16; r += 12) {
        float s = 0.0f;
        for (int c = lane; c < DIM; c += 32) s += tok[r][c];
#pragma unroll
        for (int off = 16; off; off >>= 1) s += __shfl_xor_sync(0xffffffffu, s, off);
        float mu = s * (1.0f / DIM);
        float v = 0.0f;
        for (int c = lane; c < DIM; c += 32) {
            float d0 = tok[r][c] - mu;
            v += d0 * d0;
        }
#pragma unroll
        for (int off = 16; off; off >>= 1) v += __shfl_xor_sync(0xffffffffu, v, off);
        float rstd = rsqrtf(v * (1.0f / DIM) + 1e-5f);
        for (int c = lane; c < DIM; c += 32)
            out_tok[((size_t)row0 + r) * DIM + c] =
                (tok[r][c] - mu) * rstd * gamma[c] + beta[c];
    }
}

// ---------------------------------------------------------------------------
extern "C" void kernel_launch(void* const* d_in, const int* in_sizes, int n_in,
                              void* d_out, int out_size) {
    const float* pts   = (const float*)d_in[0];  // [32,16384,3]
    const float* w1    = (const float*)d_in[1];  // [3,128]
    const float* b1    = (const float*)d_in[2];  // [128]
    const float* w2    = (const float*)d_in[3];  // [128,384]
    const float* b2    = (const float*)d_in[4];  // [384]
    const float* gamma = (const float*)d_in[5];  // [384]
    const float* beta  = (const float*)d_in[6];  // [384]

    float* out = (float*)d_out;
    float* out_cent = nullptr;
    float* out_tok = out;
    if (out_size == BATCH * GRP * (3 + DIM)) {
        out_cent = out;
        out_tok = out + BATCH * GRP * 3;
    }

    cudaFuncSetAttribute(fps_kernel, cudaFuncAttributeMaxDynamicSharedMemorySize,
                         3 * FPS_PTS * (int)sizeof(float));
    cudaFuncSetAttribute(group_kernel, cudaFuncAttributeMaxDynamicSharedMemorySize,
                         NPTS * (int)sizeof(unsigned));

    fps_kernel<<<BATCH * FPS_CTAS, FPS_THREADS, 3 * FPS_PTS * sizeof(float)>>>(pts, out_cent);
    group_kernel<<<dim3(GRP, BATCH), 512, NPTS * sizeof(unsigned)>>>(pts, w1, b1);
    head_kernel<<<(BATCH * GRP) / 16, 384>>>(w2, b2, gamma, beta, out_tok);
}